// round 10
// baseline (speedup 1.0000x reference)
#include <cuda_runtime.h>
#include <cuda_fp16.h>
#include <math.h>
#include <stdlib.h>

#define NN 100000
#define EE 300000
#define XDIM 32
#define DDIM 256
#define NLAYER 3

// ---------------- scratch: ONE big union buffer + small arrays (<128MiB total) ---
// g_big holds xl_f16 | xr_f16 [2 * N*256 halfs = 102.4MB].
__device__ float  g_big[NN * DDIM];
__device__ float  g_alpha[EE * 4];     // per-edge per-head attention logits (4.8MB)
__device__ int    g_rowptr[NN + 1];
__device__ int    g_cursor[NN];
__device__ int    g_eid[EE];
__device__ double g_red[2];            // sum, sumsq for graph-LN
__device__ float  g_stats[2];          // mu, rsigma

namespace {
struct EnvSetter {
    EnvSetter() { setenv("CUDA_MODULE_LOADING", "EAGER", 1); }
};
EnvSetter g_env_setter;
}

// ---------------- packed f32x2 FMA (Blackwell: 2x FFMA throughput) ----------------
__device__ __forceinline__ void ffma2(float2 &d, float2 a, float2 b) {
    unsigned long long &dd = *reinterpret_cast<unsigned long long *>(&d);
    unsigned long long aa = *reinterpret_cast<unsigned long long *>(&a);
    unsigned long long bb = *reinterpret_cast<unsigned long long *>(&b);
    asm("fma.rn.f32x2 %0, %1, %2, %0;" : "+l"(dd) : "l"(aa), "l"(bb));
}

// ---------------- CSR build ----------------
__global__ __launch_bounds__(256) void k_zero_cursor() {
    int i = blockIdx.x * blockDim.x + threadIdx.x;
    if (i < NN) g_cursor[i] = 0;
}

__global__ __launch_bounds__(256) void k_count(const int *__restrict__ ei) {
    int e = blockIdx.x * blockDim.x + threadIdx.x;
    if (e < EE) atomicAdd(&g_cursor[ei[EE + e]], 1);  // dst = row 1
}

__global__ __launch_bounds__(256, 1) void k_scan() {
    __shared__ int ssum[256];
    int t = threadIdx.x;
    const int CH = (NN + 255) / 256;
    int base = t * CH;
    int local = 0;
    for (int i = 0; i < CH; i++) {
        int idx = base + i;
        if (idx < NN) local += g_cursor[idx];
    }
    ssum[t] = local;
    __syncthreads();
    for (int off = 1; off < 256; off <<= 1) {
        int v = 0;
        if (t >= off) v = ssum[t - off];
        __syncthreads();
        if (t >= off) ssum[t] += v;
        __syncthreads();
    }
    int prefix = (t == 0) ? 0 : ssum[t - 1];
    for (int i = 0; i < CH; i++) {
        int idx = base + i;
        if (idx < NN) {
            int d = g_cursor[idx];
            g_rowptr[idx] = prefix;
            prefix += d;
        }
    }
    if (t == 255) g_rowptr[NN] = ssum[255];
}

__global__ __launch_bounds__(256) void k_copy_cursor() {
    int i = blockIdx.x * blockDim.x + threadIdx.x;
    if (i < NN) g_cursor[i] = g_rowptr[i];
}

__global__ __launch_bounds__(256) void k_fill(const int *__restrict__ ei) {
    int e = blockIdx.x * blockDim.x + threadIdx.x;
    if (e < EE) {
        int d = ei[EE + e];
        int pos = atomicAdd(&g_cursor[d], 1);
        g_eid[pos] = e;
    }
}

// ---------------- pre-encoder: h = relu(x @ W0 + b0) ----------------
__global__ __launch_bounds__(256) void k_preenc(const float *__restrict__ x,
                                                const float *__restrict__ W0,
                                                const float *__restrict__ b0,
                                                float *__restrict__ h) {
    int n = blockIdx.x;
    int c = threadIdx.x;
    __shared__ float sx[XDIM];
    if (c < XDIM) sx[c] = x[n * XDIM + c];
    __syncthreads();
    float acc = b0[c];
#pragma unroll
    for (int k = 0; k < XDIM; k++) acc = fmaf(sx[k], W0[k * DDIM + c], acc);
    h[n * DDIM + c] = fmaxf(acc, 0.f);
}

// ---------------- SGEMM: fp16 output into g_big (offset in halfs) ----------------
__global__ __launch_bounds__(256, 2) void k_sgemm_h(const float *__restrict__ A,
                                                    const float *__restrict__ B,
                                                    const float *__restrict__ bias,
                                                    long out_off, int M) {
    const int K = 256, NC = 256;
    __shared__ float sA[8][132];
    __shared__ float sB[8][128];
    int bm = blockIdx.x * 128;
    int bn = blockIdx.y * 128;
    int tid = threadIdx.x;
    int tx = tid & 15, ty = tid >> 4;
    int arow = tid >> 1, acol = (tid & 1) * 4;
    int brow = tid >> 5, bcol = (tid & 31) * 4;

    float2 acc[8][4];
#pragma unroll
    for (int i = 0; i < 8; i++)
#pragma unroll
        for (int j = 0; j < 4; j++) acc[i][j] = make_float2(0.f, 0.f);

    for (int k0 = 0; k0 < K; k0 += 8) {
        float4 av = make_float4(0.f, 0.f, 0.f, 0.f);
        int gr = bm + arow;
        if (gr < M) av = *(const float4 *)&A[(long)gr * K + k0 + acol];
        sA[acol + 0][arow] = av.x;
        sA[acol + 1][arow] = av.y;
        sA[acol + 2][arow] = av.z;
        sA[acol + 3][arow] = av.w;
        *(float4 *)&sB[brow][bcol] = *(const float4 *)&B[(k0 + brow) * NC + bn + bcol];
        __syncthreads();
#pragma unroll
        for (int kk = 0; kk < 8; kk++) {
            float4 a0 = *(const float4 *)&sA[kk][ty * 8];
            float4 a1 = *(const float4 *)&sA[kk][ty * 8 + 4];
            float a[8] = {a0.x, a0.y, a0.z, a0.w, a1.x, a1.y, a1.z, a1.w};
            float4 b0v = *(const float4 *)&sB[kk][tx * 8];
            float4 b1v = *(const float4 *)&sB[kk][tx * 8 + 4];
            float2 b2[4] = {make_float2(b0v.x, b0v.y), make_float2(b0v.z, b0v.w),
                            make_float2(b1v.x, b1v.y), make_float2(b1v.z, b1v.w)};
#pragma unroll
            for (int i = 0; i < 8; i++) {
                float2 ad = make_float2(a[i], a[i]);
#pragma unroll
                for (int j = 0; j < 4; j++) ffma2(acc[i][j], ad, b2[j]);
            }
        }
        __syncthreads();
    }

    __half *C = reinterpret_cast<__half *>(g_big) + out_off;
    int gc = bn + tx * 8;
    float4 bia0 = *(const float4 *)&bias[gc];
    float4 bia1 = *(const float4 *)&bias[gc + 4];
#pragma unroll
    for (int i = 0; i < 8; i++) {
        int gr = bm + ty * 8 + i;
        if (gr >= M) continue;
        __half2 h0 = __floats2half2_rn(acc[i][0].x + bia0.x, acc[i][0].y + bia0.y);
        __half2 h1 = __floats2half2_rn(acc[i][1].x + bia0.z, acc[i][1].y + bia0.w);
        __half2 h2 = __floats2half2_rn(acc[i][2].x + bia1.x, acc[i][2].y + bia1.y);
        __half2 h3 = __floats2half2_rn(acc[i][3].x + bia1.z, acc[i][3].y + bia1.w);
        uint4 pk;
        pk.x = *(unsigned *)&h0;
        pk.y = *(unsigned *)&h1;
        pk.z = *(unsigned *)&h2;
        pk.w = *(unsigned *)&h3;
        *(uint4 *)&C[(long)gr * NC + gc] = pk;
    }
}

// ---------------- edge logits: warp per edge ----------------
__global__ __launch_bounds__(256) void k_logits(const int *__restrict__ ei,
                                                const int *__restrict__ etype,
                                                const float *__restrict__ efeat,
                                                const float *__restrict__ We,
                                                const float *__restrict__ att) {
    __shared__ float sWe[4 * DDIM];
    __shared__ float sAtt[DDIM];
    int tid = threadIdx.x;
    for (int i = tid; i < 4 * DDIM; i += 256) sWe[i] = We[i];
    sAtt[tid] = att[tid];
    __syncthreads();

    int e = blockIdx.x * 8 + (tid >> 5);
    if (e >= EE) return;
    int lane = tid & 31;
    int src = ei[e];
    int dst = ei[EE + e];
    int t = etype[e];
    float f = efeat[e];

    const __half *xl = reinterpret_cast<const __half *>(g_big);
    const __half *xr = xl + (long)NN * DDIM;
    int c0 = lane * 8;
    uint4 pl = *(const uint4 *)&xl[(long)src * DDIM + c0];
    uint4 pr = *(const uint4 *)&xr[(long)dst * DDIM + c0];
    const __half2 *hl = (const __half2 *)&pl;
    const __half2 *hr = (const __half2 *)&pr;

    float part = 0.f;
#pragma unroll
    for (int q = 0; q < 4; q++) {
        float2 a2 = __half22float2(hl[q]);
        float2 b2 = __half22float2(hr[q]);
        int c = c0 + q * 2;
        float y0 = a2.x + b2.x + sWe[t * DDIM + c] + f * sWe[3 * DDIM + c];
        float y1 = a2.y + b2.y + sWe[t * DDIM + c + 1] + f * sWe[3 * DDIM + c + 1];
        y0 = (y0 > 0.f) ? y0 : 0.2f * y0;
        y1 = (y1 > 0.f) ? y1 : 0.2f * y1;
        part = fmaf(sAtt[c], y0, part);
        part = fmaf(sAtt[c + 1], y1, part);
    }
#pragma unroll
    for (int off = 4; off; off >>= 1) part += __shfl_xor_sync(0xffffffffu, part, off);
    if ((lane & 7) == 0) g_alpha[e * 4 + (lane >> 3)] = part;
}

// ---- softmax + per-head aggregation of xl_f16 + bo + relu + LN partials -> d_out ----
// Correct per-head semantics: channel c belongs to head c/64, and this warp layout
// gives lane channels c0=lane*8..c0+7 all in head (lane>>3) — the weight a[e,head]
// multiplies xl's own channels, exactly matching msg = xl[src] * a[:,head,None].
__global__ __launch_bounds__(256) void k_agg_out(const int *__restrict__ srcArr,
                                                 const float *__restrict__ bo,
                                                 float *__restrict__ out) {
    __shared__ float sBo[DDIM];
    __shared__ double sRed[8][2];
    int tid = threadIdx.x;
    sBo[tid] = bo[tid];
    __syncthreads();

    int warp = tid >> 5, lane = tid & 31;
    int n = blockIdx.x * 8 + warp;
    double lsum = 0.0, lsq = 0.0;

    if (n < NN) {
        int hd = lane >> 3;
        int c0 = lane * 8;
        int p0 = g_rowptr[n], p1 = g_rowptr[n + 1];

        // pass 1: max logit for this head
        float m = -INFINITY, s = 0.f;
        for (int p = p0; p < p1; p++) {
            float a = g_alpha[g_eid[p] * 4 + hd];
            float mn = fmaxf(m, a);
            s = s * expf(m - mn) + expf(a - mn);
            m = mn;
        }
        float inv_s = (p1 > p0) ? 1.f / s : 0.f;

        // pass 2: weighted aggregation of xl_f16
        const __half *xl = reinterpret_cast<const __half *>(g_big);
        float acc[8] = {0.f, 0.f, 0.f, 0.f, 0.f, 0.f, 0.f, 0.f};
        for (int p = p0; p < p1; p++) {
            int e = g_eid[p];
            int src = srcArr[e];
            float a = g_alpha[e * 4 + hd];
            float w = expf(a - m) * inv_s;
            uint4 pk = *(const uint4 *)&xl[(long)src * DDIM + c0];
            const __half2 *hh = (const __half2 *)&pk;
#pragma unroll
            for (int q = 0; q < 4; q++) {
                float2 v = __half22float2(hh[q]);
                acc[2 * q] = fmaf(w, v.x, acc[2 * q]);
                acc[2 * q + 1] = fmaf(w, v.y, acc[2 * q + 1]);
            }
        }

        float v[8];
#pragma unroll
        for (int j = 0; j < 8; j++) {
            float t2 = acc[j] + sBo[c0 + j];
            t2 = fmaxf(t2, 0.f);  // relu before LN
            v[j] = t2;
            lsum += (double)t2;
            lsq += (double)t2 * (double)t2;
        }
        *(float4 *)&out[(long)n * DDIM + c0] = make_float4(v[0], v[1], v[2], v[3]);
        *(float4 *)&out[(long)n * DDIM + c0 + 4] = make_float4(v[4], v[5], v[6], v[7]);
    }

#pragma unroll
    for (int off = 16; off; off >>= 1) {
        lsum += __shfl_xor_sync(0xffffffffu, lsum, off);
        lsq += __shfl_xor_sync(0xffffffffu, lsq, off);
    }
    if (lane == 0) {
        sRed[warp][0] = lsum;
        sRed[warp][1] = lsq;
    }
    __syncthreads();
    if (tid == 0) {
        double a = 0.0, b = 0.0;
        for (int w = 0; w < 8; w++) {
            a += sRed[w][0];
            b += sRed[w][1];
        }
        atomicAdd(&g_red[0], a);
        atomicAdd(&g_red[1], b);
    }
}

// ---------------- LN reset / finalize / apply ----------------
__global__ __launch_bounds__(32) void k_reset() {
    if (threadIdx.x == 0) {
        g_red[0] = 0.0;
        g_red[1] = 0.0;
    }
}

__global__ __launch_bounds__(32) void k_finalize() {
    const double cnt = (double)NN * (double)DDIM;
    double mu = g_red[0] / cnt;
    double var = g_red[1] / cnt - mu * mu;
    g_stats[0] = (float)mu;
    g_stats[1] = (float)rsqrt(var + 1e-5);
}

__global__ __launch_bounds__(256) void k_norm(float *__restrict__ h,
                                              const float *__restrict__ gamma,
                                              const float *__restrict__ beta) {
    long i = (long)blockIdx.x * blockDim.x + threadIdx.x;
    if (i >= (long)NN * (DDIM / 4)) return;
    float mu = g_stats[0], rs = g_stats[1];
    float4 v = ((float4 *)h)[i];
    int cb = ((int)(i & 63)) * 4;
    float4 ga = *(const float4 *)&gamma[cb];
    float4 be = *(const float4 *)&beta[cb];
    v.x = (v.x - mu) * rs * ga.x + be.x;
    v.y = (v.y - mu) * rs * ga.y + be.y;
    v.z = (v.z - mu) * rs * ga.z + be.z;
    v.w = (v.w - mu) * rs * ga.w + be.w;
    ((float4 *)h)[i] = v;
}

// ---------------- launch ----------------
extern "C" void kernel_launch(void *const *d_in, const int *in_sizes, int n_in,
                              void *d_out, int out_size) {
    const float *x = (const float *)d_in[0];
    const int *ei = (const int *)d_in[1];  // [2,E]: row0=src, row1=dst
    const int *et = (const int *)d_in[2];
    const float *ef = (const float *)d_in[3];
    const float *W0 = (const float *)d_in[4];
    const float *b0 = (const float *)d_in[5];
    const float *Wl = (const float *)d_in[6];
    const float *bl = (const float *)d_in[7];
    const float *Wr = (const float *)d_in[8];
    const float *br = (const float *)d_in[9];
    const float *We = (const float *)d_in[10];
    const float *att = (const float *)d_in[11];
    const float *bo = (const float *)d_in[12];
    const float *gamma = (const float *)d_in[13];
    const float *beta = (const float *)d_in[14];
    float *out = (float *)d_out;

    // CSR build
    k_zero_cursor<<<(NN + 255) / 256, 256>>>();
    k_count<<<(EE + 255) / 256, 256>>>(ei);
    k_scan<<<1, 256>>>();
    k_copy_cursor<<<(NN + 255) / 256, 256>>>();
    k_fill<<<(EE + 255) / 256, 256>>>(ei);

    // pre-encoder: h -> d_out
    k_preenc<<<NN, DDIM>>>(x, W0, b0, out);

    dim3 ggrid((NN + 127) / 128, 2);
    for (int l = 0; l < NLAYER; l++) {
        const float *Wli = Wl + (long)l * DDIM * DDIM;
        const float *Wri = Wr + (long)l * DDIM * DDIM;
        // xl_f16 / xr_f16 into the two halves of g_big (read h from d_out)
        k_sgemm_h<<<ggrid, 256>>>(out, Wli, bl + l * DDIM, 0, NN);
        k_sgemm_h<<<ggrid, 256>>>(out, Wri, br + l * DDIM, (long)NN * DDIM, NN);
        // per-edge logits from xl_f16/xr_f16
        k_logits<<<(EE + 7) / 8, 256>>>(ei, et, ef, We + (long)l * 4 * DDIM,
                                        att + (long)l * DDIM);
        // softmax + aggregate xl_f16 + bo + relu + LN partials -> d_out (h is dead)
        k_reset<<<1, 32>>>();
        k_agg_out<<<(NN + 7) / 8, 256>>>(ei, bo + l * DDIM, out);
        // graph-LN in place
        k_finalize<<<1, 1>>>();
        k_norm<<<(NN * (DDIM / 4) + 255) / 256, 256>>>(out, gamma, beta);
    }
}

// round 11
// speedup vs baseline: 1.7959x; 1.7959x over previous
#include <cuda_runtime.h>
#include <cuda_fp16.h>
#include <math.h>
#include <stdlib.h>

#define NN 100000
#define EE 300000
#define XDIM 32
#define DDIM 256
#define NLAYER 3

// ---------------- scratch: <128MiB total ----------------
__device__ float  g_big[NN * DDIM];    // xl_f16 | xr_f16 (as halfs)
__device__ float  g_alpha[EE * 4];
__device__ int    g_rowptr[NN + 1];
__device__ int    g_cursor[NN];
__device__ int    g_eid[EE];
__device__ double g_red[2];
__device__ float  g_stats[2];

namespace {
struct EnvSetter {
    EnvSetter() { setenv("CUDA_MODULE_LOADING", "EAGER", 1); }
};
EnvSetter g_env_setter;
}

// ---------------- CSR build ----------------
__global__ __launch_bounds__(256) void k_zero_cursor() {
    int i = blockIdx.x * blockDim.x + threadIdx.x;
    if (i < NN) g_cursor[i] = 0;
}

__global__ __launch_bounds__(256) void k_count(const int *__restrict__ ei) {
    int e = blockIdx.x * blockDim.x + threadIdx.x;
    if (e < EE) atomicAdd(&g_cursor[ei[EE + e]], 1);
}

__global__ __launch_bounds__(256, 1) void k_scan() {
    __shared__ int ssum[256];
    int t = threadIdx.x;
    const int CH = (NN + 255) / 256;
    int base = t * CH;
    int local = 0;
    for (int i = 0; i < CH; i++) {
        int idx = base + i;
        if (idx < NN) local += g_cursor[idx];
    }
    ssum[t] = local;
    __syncthreads();
    for (int off = 1; off < 256; off <<= 1) {
        int v = 0;
        if (t >= off) v = ssum[t - off];
        __syncthreads();
        if (t >= off) ssum[t] += v;
        __syncthreads();
    }
    int prefix = (t == 0) ? 0 : ssum[t - 1];
    for (int i = 0; i < CH; i++) {
        int idx = base + i;
        if (idx < NN) {
            int d = g_cursor[idx];
            g_rowptr[idx] = prefix;
            prefix += d;
        }
    }
    if (t == 255) g_rowptr[NN] = ssum[255];
}

__global__ __launch_bounds__(256) void k_copy_cursor() {
    int i = blockIdx.x * blockDim.x + threadIdx.x;
    if (i < NN) g_cursor[i] = g_rowptr[i];
}

__global__ __launch_bounds__(256) void k_fill(const int *__restrict__ ei) {
    int e = blockIdx.x * blockDim.x + threadIdx.x;
    if (e < EE) {
        int d = ei[EE + e];
        int pos = atomicAdd(&g_cursor[d], 1);
        g_eid[pos] = e;
    }
}

// ---------------- pre-encoder ----------------
__global__ __launch_bounds__(256) void k_preenc(const float *__restrict__ x,
                                                const float *__restrict__ W0,
                                                const float *__restrict__ b0,
                                                float *__restrict__ h) {
    int n = blockIdx.x;
    int c = threadIdx.x;
    __shared__ float sx[XDIM];
    if (c < XDIM) sx[c] = x[n * XDIM + c];
    __syncthreads();
    float acc = b0[c];
#pragma unroll
    for (int k = 0; k < XDIM; k++) acc = fmaf(sx[k], W0[k * DDIM + c], acc);
    h[n * DDIM + c] = fmaxf(acc, 0.f);
}

// ---------------- tensor-core HGEMM: C_f16 = f16(A_f32) @ f16(B_f32) + bias ------
// A [M,256] fp32 row-major; B [256,256] fp32 row-major; C fp16 into g_big.
// blockIdx.z selects (Wl, bl, xl-half) vs (Wr, br, xr-half).
#define BM 128
#define BN 128
#define BK 32

__device__ __forceinline__ unsigned smem_u32(const void *p) {
    return (unsigned)__cvta_generic_to_shared(p);
}

__global__ __launch_bounds__(256, 2) void k_hgemm(const float *__restrict__ A,
                                                  const float *__restrict__ Wl,
                                                  const float *__restrict__ Wr,
                                                  const float *__restrict__ blp,
                                                  const float *__restrict__ brp,
                                                  int M) {
    __shared__ __half sA[BM][BK + 8];   // stride 80B: ldmatrix conflict-free
    __shared__ __half sB[BK][BN + 8];   // stride 272B

    const float *B = blockIdx.z ? Wr : Wl;
    const float *bias = blockIdx.z ? brp : blp;
    __half *C = reinterpret_cast<__half *>(g_big) + (long)blockIdx.z * NN * DDIM;

    int tid = threadIdx.x;
    int warp = tid >> 5, lane = tid & 31;
    int bm = blockIdx.x * BM;
    int bn = blockIdx.y * BN;
    int wm = (warp & 3) * 32;   // warp row offset in tile
    int wn = (warp >> 2) * 64;  // warp col offset in tile

    float acc[2][8][4];
#pragma unroll
    for (int mi = 0; mi < 2; mi++)
#pragma unroll
        for (int ni = 0; ni < 8; ni++)
#pragma unroll
            for (int q = 0; q < 4; q++) acc[mi][ni][q] = 0.f;

    int ar = tid >> 1, ac = (tid & 1) * 16;   // A: 128 rows x 32 cols
    int br_ = tid >> 3, bc = (tid & 7) * 16;  // B: 32 rows x 128 cols
    bool avalid = (bm + ar) < M;

    for (int k0 = 0; k0 < 256; k0 += BK) {
        // ---- load A tile (fp32 -> fp16) ----
        {
            float4 f0 = make_float4(0, 0, 0, 0), f1 = f0, f2 = f0, f3 = f0;
            if (avalid) {
                const float4 *ap = (const float4 *)&A[(long)(bm + ar) * 256 + k0 + ac];
                f0 = ap[0]; f1 = ap[1]; f2 = ap[2]; f3 = ap[3];
            }
            __half2 h0 = __floats2half2_rn(f0.x, f0.y), h1 = __floats2half2_rn(f0.z, f0.w);
            __half2 h2 = __floats2half2_rn(f1.x, f1.y), h3 = __floats2half2_rn(f1.z, f1.w);
            __half2 h4 = __floats2half2_rn(f2.x, f2.y), h5 = __floats2half2_rn(f2.z, f2.w);
            __half2 h6 = __floats2half2_rn(f3.x, f3.y), h7 = __floats2half2_rn(f3.z, f3.w);
            uint4 p0, p1;
            p0.x = *(unsigned *)&h0; p0.y = *(unsigned *)&h1;
            p0.z = *(unsigned *)&h2; p0.w = *(unsigned *)&h3;
            p1.x = *(unsigned *)&h4; p1.y = *(unsigned *)&h5;
            p1.z = *(unsigned *)&h6; p1.w = *(unsigned *)&h7;
            *(uint4 *)&sA[ar][ac] = p0;
            *(uint4 *)&sA[ar][ac + 8] = p1;
        }
        // ---- load B tile (fp32 -> fp16) ----
        {
            const float4 *bp = (const float4 *)&B[(long)(k0 + br_) * 256 + bn + bc];
            float4 f0 = bp[0], f1 = bp[1], f2 = bp[2], f3 = bp[3];
            __half2 h0 = __floats2half2_rn(f0.x, f0.y), h1 = __floats2half2_rn(f0.z, f0.w);
            __half2 h2 = __floats2half2_rn(f1.x, f1.y), h3 = __floats2half2_rn(f1.z, f1.w);
            __half2 h4 = __floats2half2_rn(f2.x, f2.y), h5 = __floats2half2_rn(f2.z, f2.w);
            __half2 h6 = __floats2half2_rn(f3.x, f3.y), h7 = __floats2half2_rn(f3.z, f3.w);
            uint4 p0, p1;
            p0.x = *(unsigned *)&h0; p0.y = *(unsigned *)&h1;
            p0.z = *(unsigned *)&h2; p0.w = *(unsigned *)&h3;
            p1.x = *(unsigned *)&h4; p1.y = *(unsigned *)&h5;
            p1.z = *(unsigned *)&h6; p1.w = *(unsigned *)&h7;
            *(uint4 *)&sB[br_][bc] = p0;
            *(uint4 *)&sB[br_][bc + 8] = p1;
        }
        __syncthreads();

#pragma unroll
        for (int kk = 0; kk < 2; kk++) {
            int ks = kk * 16;
            // A fragments: 2 m16-tiles (ldmatrix x4, non-trans)
            unsigned af[2][4];
#pragma unroll
            for (int mi = 0; mi < 2; mi++) {
                int row = wm + mi * 16 + (lane & 15);
                int col = ks + ((lane >> 4) << 3);
                unsigned addr = smem_u32(&sA[row][col]);
                asm volatile(
                    "ldmatrix.sync.aligned.m8n8.x4.shared.b16 {%0,%1,%2,%3}, [%4];"
                    : "=r"(af[mi][0]), "=r"(af[mi][1]), "=r"(af[mi][2]), "=r"(af[mi][3])
                    : "r"(addr));
            }
            // B fragments: 8 n8-tiles via 4 ldmatrix x4.trans (n16 each)
            unsigned bf[8][2];
#pragma unroll
            for (int g = 0; g < 4; g++) {
                int row = ks + (lane & 15);
                int col = wn + g * 16 + ((lane >> 4) << 3);
                unsigned addr = smem_u32(&sB[row][col]);
                unsigned r0, r1, r2, r3;
                asm volatile(
                    "ldmatrix.sync.aligned.m8n8.x4.trans.shared.b16 {%0,%1,%2,%3}, [%4];"
                    : "=r"(r0), "=r"(r1), "=r"(r2), "=r"(r3)
                    : "r"(addr));
                bf[g * 2][0] = r0; bf[g * 2][1] = r1;
                bf[g * 2 + 1][0] = r2; bf[g * 2 + 1][1] = r3;
            }
#pragma unroll
            for (int mi = 0; mi < 2; mi++)
#pragma unroll
                for (int ni = 0; ni < 8; ni++) {
                    asm volatile(
                        "mma.sync.aligned.m16n8k16.row.col.f32.f16.f16.f32 "
                        "{%0,%1,%2,%3}, {%4,%5,%6,%7}, {%8,%9}, {%0,%1,%2,%3};"
                        : "+f"(acc[mi][ni][0]), "+f"(acc[mi][ni][1]),
                          "+f"(acc[mi][ni][2]), "+f"(acc[mi][ni][3])
                        : "r"(af[mi][0]), "r"(af[mi][1]), "r"(af[mi][2]), "r"(af[mi][3]),
                          "r"(bf[ni][0]), "r"(bf[ni][1]));
                }
        }
        __syncthreads();
    }

    // ---- epilogue: +bias, fp16, store ----
#pragma unroll
    for (int ni = 0; ni < 8; ni++) {
        int coln = bn + wn + ni * 8 + (lane & 3) * 2;
        float2 bv = *(const float2 *)&bias[coln];
#pragma unroll
        for (int mi = 0; mi < 2; mi++) {
            int row0 = bm + wm + mi * 16 + (lane >> 2);
            int row1 = row0 + 8;
            __half2 h01 = __floats2half2_rn(acc[mi][ni][0] + bv.x, acc[mi][ni][1] + bv.y);
            __half2 h23 = __floats2half2_rn(acc[mi][ni][2] + bv.x, acc[mi][ni][3] + bv.y);
            if (row0 < M) *(__half2 *)&C[(long)row0 * 256 + coln] = h01;
            if (row1 < M) *(__half2 *)&C[(long)row1 * 256 + coln] = h23;
        }
    }
}

// ---------------- edge logits: warp per edge ----------------
__global__ __launch_bounds__(256) void k_logits(const int *__restrict__ ei,
                                                const int *__restrict__ etype,
                                                const float *__restrict__ efeat,
                                                const float *__restrict__ We,
                                                const float *__restrict__ att) {
    __shared__ float sWe[4 * DDIM];
    __shared__ float sAtt[DDIM];
    int tid = threadIdx.x;
    for (int i = tid; i < 4 * DDIM; i += 256) sWe[i] = We[i];
    sAtt[tid] = att[tid];
    __syncthreads();

    int e = blockIdx.x * 8 + (tid >> 5);
    if (e >= EE) return;
    int lane = tid & 31;
    int src = ei[e];
    int dst = ei[EE + e];
    int t = etype[e];
    float f = efeat[e];

    const __half *xl = reinterpret_cast<const __half *>(g_big);
    const __half *xr = xl + (long)NN * DDIM;
    int c0 = lane * 8;
    uint4 pl = *(const uint4 *)&xl[(long)src * DDIM + c0];
    uint4 pr = *(const uint4 *)&xr[(long)dst * DDIM + c0];
    const __half2 *hl = (const __half2 *)&pl;
    const __half2 *hr = (const __half2 *)&pr;

    float part = 0.f;
#pragma unroll
    for (int q = 0; q < 4; q++) {
        float2 a2 = __half22float2(hl[q]);
        float2 b2 = __half22float2(hr[q]);
        int c = c0 + q * 2;
        float y0 = a2.x + b2.x + sWe[t * DDIM + c] + f * sWe[3 * DDIM + c];
        float y1 = a2.y + b2.y + sWe[t * DDIM + c + 1] + f * sWe[3 * DDIM + c + 1];
        y0 = (y0 > 0.f) ? y0 : 0.2f * y0;
        y1 = (y1 > 0.f) ? y1 : 0.2f * y1;
        part = fmaf(sAtt[c], y0, part);
        part = fmaf(sAtt[c + 1], y1, part);
    }
#pragma unroll
    for (int off = 4; off; off >>= 1) part += __shfl_xor_sync(0xffffffffu, part, off);
    if ((lane & 7) == 0) g_alpha[e * 4 + (lane >> 3)] = part;
}

// ---- softmax + per-head aggregation of xl_f16 + bo + relu + LN partials ----
__global__ __launch_bounds__(256) void k_agg_out(const int *__restrict__ srcArr,
                                                 const float *__restrict__ bo,
                                                 float *__restrict__ out) {
    __shared__ float sBo[DDIM];
    __shared__ double sRed[8][2];
    int tid = threadIdx.x;
    sBo[tid] = bo[tid];
    __syncthreads();

    int warp = tid >> 5, lane = tid & 31;
    int n = blockIdx.x * 8 + warp;
    double lsum = 0.0, lsq = 0.0;

    if (n < NN) {
        int hd = lane >> 3;
        int c0 = lane * 8;
        int p0 = g_rowptr[n], p1 = g_rowptr[n + 1];

        float m = -INFINITY, s = 0.f;
        for (int p = p0; p < p1; p++) {
            float a = g_alpha[g_eid[p] * 4 + hd];
            float mn = fmaxf(m, a);
            s = s * expf(m - mn) + expf(a - mn);
            m = mn;
        }
        float inv_s = (p1 > p0) ? 1.f / s : 0.f;

        const __half *xl = reinterpret_cast<const __half *>(g_big);
        float acc[8] = {0.f, 0.f, 0.f, 0.f, 0.f, 0.f, 0.f, 0.f};
        for (int p = p0; p < p1; p++) {
            int e = g_eid[p];
            int src = srcArr[e];
            float a = g_alpha[e * 4 + hd];
            float w = expf(a - m) * inv_s;
            uint4 pk = *(const uint4 *)&xl[(long)src * DDIM + c0];
            const __half2 *hh = (const __half2 *)&pk;
#pragma unroll
            for (int q = 0; q < 4; q++) {
                float2 v = __half22float2(hh[q]);
                acc[2 * q] = fmaf(w, v.x, acc[2 * q]);
                acc[2 * q + 1] = fmaf(w, v.y, acc[2 * q + 1]);
            }
        }

        float v[8];
#pragma unroll
        for (int j = 0; j < 8; j++) {
            float t2 = acc[j] + sBo[c0 + j];
            t2 = fmaxf(t2, 0.f);
            v[j] = t2;
            lsum += (double)t2;
            lsq += (double)t2 * (double)t2;
        }
        *(float4 *)&out[(long)n * DDIM + c0] = make_float4(v[0], v[1], v[2], v[3]);
        *(float4 *)&out[(long)n * DDIM + c0 + 4] = make_float4(v[4], v[5], v[6], v[7]);
    }

#pragma unroll
    for (int off = 16; off; off >>= 1) {
        lsum += __shfl_xor_sync(0xffffffffu, lsum, off);
        lsq += __shfl_xor_sync(0xffffffffu, lsq, off);
    }
    if (lane == 0) {
        sRed[warp][0] = lsum;
        sRed[warp][1] = lsq;
    }
    __syncthreads();
    if (tid == 0) {
        double a = 0.0, b = 0.0;
        for (int w = 0; w < 8; w++) {
            a += sRed[w][0];
            b += sRed[w][1];
        }
        atomicAdd(&g_red[0], a);
        atomicAdd(&g_red[1], b);
    }
}

// ---------------- LN reset / finalize / apply ----------------
__global__ __launch_bounds__(32) void k_reset() {
    if (threadIdx.x == 0) {
        g_red[0] = 0.0;
        g_red[1] = 0.0;
    }
}

__global__ __launch_bounds__(32) void k_finalize() {
    const double cnt = (double)NN * (double)DDIM;
    double mu = g_red[0] / cnt;
    double var = g_red[1] / cnt - mu * mu;
    g_stats[0] = (float)mu;
    g_stats[1] = (float)rsqrt(var + 1e-5);
}

__global__ __launch_bounds__(256) void k_norm(float *__restrict__ h,
                                              const float *__restrict__ gamma,
                                              const float *__restrict__ beta) {
    long i = (long)blockIdx.x * blockDim.x + threadIdx.x;
    if (i >= (long)NN * (DDIM / 4)) return;
    float mu = g_stats[0], rs = g_stats[1];
    float4 v = ((float4 *)h)[i];
    int cb = ((int)(i & 63)) * 4;
    float4 ga = *(const float4 *)&gamma[cb];
    float4 be = *(const float4 *)&beta[cb];
    v.x = (v.x - mu) * rs * ga.x + be.x;
    v.y = (v.y - mu) * rs * ga.y + be.y;
    v.z = (v.z - mu) * rs * ga.z + be.z;
    v.w = (v.w - mu) * rs * ga.w + be.w;
    ((float4 *)h)[i] = v;
}

// ---------------- launch ----------------
extern "C" void kernel_launch(void *const *d_in, const int *in_sizes, int n_in,
                              void *d_out, int out_size) {
    const float *x = (const float *)d_in[0];
    const int *ei = (const int *)d_in[1];
    const int *et = (const int *)d_in[2];
    const float *ef = (const float *)d_in[3];
    const float *W0 = (const float *)d_in[4];
    const float *b0 = (const float *)d_in[5];
    const float *Wl = (const float *)d_in[6];
    const float *bl = (const float *)d_in[7];
    const float *Wr = (const float *)d_in[8];
    const float *br = (const float *)d_in[9];
    const float *We = (const float *)d_in[10];
    const float *att = (const float *)d_in[11];
    const float *bo = (const float *)d_in[12];
    const float *gamma = (const float *)d_in[13];
    const float *beta = (const float *)d_in[14];
    float *out = (float *)d_out;

    // CSR build
    k_zero_cursor<<<(NN + 255) / 256, 256>>>();
    k_count<<<(EE + 255) / 256, 256>>>(ei);
    k_scan<<<1, 256>>>();
    k_copy_cursor<<<(NN + 255) / 256, 256>>>();
    k_fill<<<(EE + 255) / 256, 256>>>(ei);

    // pre-encoder: h -> d_out
    k_preenc<<<NN, DDIM>>>(x, W0, b0, out);

    dim3 gg((NN + BM - 1) / BM, 2, 2);  // x: M-tiles, y: N-tiles, z: Wl/Wr
    for (int l = 0; l < NLAYER; l++) {
        k_hgemm<<<gg, 256>>>(out, Wl + (long)l * DDIM * DDIM, Wr + (long)l * DDIM * DDIM,
                             bl + l * DDIM, br + l * DDIM, NN);
        k_logits<<<(EE + 7) / 8, 256>>>(ei, et, ef, We + (long)l * 4 * DDIM,
                                        att + (long)l * DDIM);
        k_reset<<<1, 32>>>();
        k_agg_out<<<(NN + 7) / 8, 256>>>(ei, bo + l * DDIM, out);
        k_finalize<<<1, 1>>>();
        k_norm<<<(NN * (DDIM / 4) + 255) / 256, 256>>>(out, gamma, beta);
    }
}